// round 2
// baseline (speedup 1.0000x reference)
#include <cuda_runtime.h>
#include <cstdint>

#define NB 8
#define LQ 8192
#define SK 8192
#define HH 8
#define DD 32
#define NH (NB*HH)
#define EPSV 1e-6f

#define CHUNKS 8
#define SROWS (SK / CHUNKS)   // 1024 s-rows per block
#define TS 64                 // smem tile rows
#define TILES (SROWS / TS)    // 16
#define LT 256                // l-rows per pass2 block

// Scratch (device globals: no allocation allowed)
__device__ __align__(16) float g_KV[NH * DD * DD];   // [nh][d][v]
__device__ __align__(16) float g_Ksum[NH * DD];      // [nh][d]

__device__ __forceinline__ float elu1(float x) {
    // elu(x)+1 : x>0 -> x+1 ; x<=0 -> exp(x)
    return x > 0.f ? x + 1.f : __expf(x);
}

// packed f32x2 FMA (FFMA2) — only reachable via PTX
__device__ __forceinline__ void fma2(unsigned long long &acc,
                                     unsigned long long a,
                                     unsigned long long b) {
    asm("fma.rn.f32x2 %0, %1, %2, %0;" : "+l"(acc) : "l"(a), "l"(b));
}
__device__ __forceinline__ unsigned long long pk(float x, float y) {
    unsigned long long r;
    asm("mov.b64 %0, {%1,%2};" : "=l"(r) : "f"(x), "f"(y));
    return r;
}
__device__ __forceinline__ float2 upk(unsigned long long v) {
    float2 r;
    asm("mov.b64 {%0,%1}, %2;" : "=f"(r.x), "=f"(r.y) : "l"(v));
    return r;
}

__global__ void zero_kernel() {
    int i = blockIdx.x * blockDim.x + threadIdx.x;
    if (i < NH * DD * DD) g_KV[i] = 0.f;
    if (i < NH * DD)      g_Ksum[i] = 0.f;
}

// ---------------------------------------------------------------------------
// Pass 1: KV[nh] += sum_s outer(eluK_s, v_s);  Ksum[nh] += sum_s eluK_s
// grid (CHUNKS, NH), 256 threads = 8 warps; each warp = full 32x32 replica
// over its own s-rows; per-lane tile 4(d) x 8(v) done as 16 FFMA2.
// ---------------------------------------------------------------------------
__global__ __launch_bounds__(256) void pass1(const float* __restrict__ keys,
                                             const float* __restrict__ values) {
    __shared__ __align__(16) float2 sKd[TS][DD];   // dup-K: (k,k) pairs, 16KB
    __shared__ __align__(16) float  sV [TS][DD];   // 8KB
    __shared__ __align__(16) float  sRed[8][512];  // 16KB reduction staging
    __shared__ __align__(16) float4 sKsum[256];    // 4KB

    const int nh = blockIdx.y;
    const int n = nh / HH, h = nh % HH;
    const int chunk = blockIdx.x;
    const int tid = threadIdx.x;
    const int w = tid >> 5, lane = tid & 31;
    const int d0 = (lane >> 2) * 4;   // 0,4,...,28
    const int v0 = (lane & 3) * 8;    // 0,8,16,24

    unsigned long long acc[4][4];
#pragma unroll
    for (int i = 0; i < 4; ++i)
#pragma unroll
        for (int j = 0; j < 4; ++j) acc[i][j] = 0ull;
    float4 ksacc = make_float4(0.f, 0.f, 0.f, 0.f);

    const size_t base = ((size_t)n * SK * HH + h) * DD;   // offset of (n, s=0, h, 0)
    const int rowstride = HH * DD;                        // 256 floats between s-rows
    const int s_begin = chunk * SROWS;

    for (int t = 0; t < TILES; ++t) {
        const int s0 = s_begin + t * TS;
        // cooperative load of 64x32 K (elu'd, duplicated) and V tiles
#pragma unroll
        for (int i = 0; i < 2; ++i) {
            const int f = tid + 256 * i;     // float4 index 0..511
            const int r = f >> 3;            // row 0..63
            const int c4 = (f & 7) * 4;      // col 0..28
            const float4 kq = *(const float4*)(keys + base + (size_t)(s0 + r) * rowstride + c4);
            const float k0 = elu1(kq.x), k1 = elu1(kq.y), k2 = elu1(kq.z), k3 = elu1(kq.w);
            *(float4*)&sKd[r][c4]     = make_float4(k0, k0, k1, k1);
            *(float4*)&sKd[r][c4 + 2] = make_float4(k2, k2, k3, k3);
            ksacc.x += k0; ksacc.y += k1; ksacc.z += k2; ksacc.w += k3;
            const float4 vv = *(const float4*)(values + base + (size_t)(s0 + r) * rowstride + c4);
            *(float4*)&sV[r][c4] = vv;
        }
        __syncthreads();
        // compute: warp w owns rows [w*8, w*8+8)
#pragma unroll
        for (int rr = 0; rr < 8; ++rr) {
            const int s = w * 8 + rr;
            const ulonglong2 ka = *(const ulonglong2*)&sKd[s][d0];      // (k0,k0),(k1,k1)
            const ulonglong2 kb = *(const ulonglong2*)&sKd[s][d0 + 2];  // (k2,k2),(k3,k3)
            const ulonglong2 va = *(const ulonglong2*)&sV[s][v0];       // (v0,v1),(v2,v3)
            const ulonglong2 vb = *(const ulonglong2*)&sV[s][v0 + 4];   // (v4,v5),(v6,v7)
            const unsigned long long kk[4] = {ka.x, ka.y, kb.x, kb.y};
            const unsigned long long vv[4] = {va.x, va.y, vb.x, vb.y};
#pragma unroll
            for (int i = 0; i < 4; ++i)
#pragma unroll
                for (int j = 0; j < 4; ++j) fma2(acc[i][j], kk[i], vv[j]);
        }
        __syncthreads();
    }

    // reduce the 8 warp replicas in smem, then atomicAdd to global KV
    for (int half = 0; half < 2; ++half) {
        if ((d0 >> 4) == half) {
            const int dl = d0 & 15;
#pragma unroll
            for (int i = 0; i < 4; ++i) {
                float* dst = &sRed[w][(dl + i) * DD + v0];
                *(ulonglong2*)dst       = make_ulonglong2(acc[i][0], acc[i][1]);
                *(ulonglong2*)(dst + 4) = make_ulonglong2(acc[i][2], acc[i][3]);
            }
        }
        __syncthreads();
        for (int e = tid; e < 512; e += 256) {
            float ssum = 0.f;
#pragma unroll
            for (int ww = 0; ww < 8; ++ww) ssum += sRed[ww][e];
            const int d = half * 16 + e / DD;
            const int v = e % DD;
            atomicAdd(&g_KV[(nh * DD + d) * DD + v], ssum);
        }
        __syncthreads();
    }

    // Ksum: thread t accumulated d-cols (t%8)*4..+3 over its loaded rows
    sKsum[tid] = ksacc;
    __syncthreads();
    if (tid < DD) {
        const int cgrp = tid >> 2;   // t%8 group that owns this d
        const int comp = tid & 3;
        float ssum = 0.f;
        for (int k = 0; k < 32; ++k) {
            const float4 vk = sKsum[cgrp + 8 * k];
            ssum += (comp == 0) ? vk.x : (comp == 1) ? vk.y : (comp == 2) ? vk.z : vk.w;
        }
        atomicAdd(&g_Ksum[nh * DD + tid], ssum);
    }
}

// ---------------------------------------------------------------------------
// Pass 2: out[l,:] = (eluQ[l,:] @ KV) / (eluQ[l,:].Ksum + eps)
// grid (LQ/LT, NH), 256 threads, 1 l-row per thread; KV broadcast from smem.
// ---------------------------------------------------------------------------
__global__ __launch_bounds__(256) void pass2(const float* __restrict__ queries,
                                             float* __restrict__ out) {
    __shared__ __align__(16) unsigned long long sKV[DD][DD / 2];  // (v-pairs), 4KB
    __shared__ __align__(16) float sKsF[DD];

    const int nh = blockIdx.y;
    const int n = nh / HH, h = nh % HH;
    const int tid = threadIdx.x;
    const int l = blockIdx.x * LT + tid;

    const float* kvsrc = &g_KV[nh * DD * DD];
#pragma unroll
    for (int i = 0; i < 2; ++i) {
        const int p = tid + 256 * i;  // 0..511 u64s
        ((unsigned long long*)sKV)[p] = ((const unsigned long long*)kvsrc)[p];
    }
    if (tid < DD) sKsF[tid] = g_Ksum[nh * DD + tid];
    __syncthreads();

    // Q row -> registers with elu applied
    const float* qrow = queries + ((size_t)n * LQ + l) * (HH * DD) + h * DD;
    float q[DD];
#pragma unroll
    for (int i = 0; i < 8; ++i) {
        const float4 t4 = *(const float4*)(qrow + i * 4);
        q[i * 4 + 0] = elu1(t4.x);
        q[i * 4 + 1] = elu1(t4.y);
        q[i * 4 + 2] = elu1(t4.z);
        q[i * 4 + 3] = elu1(t4.w);
    }

    float z = EPSV;
#pragma unroll
    for (int d = 0; d < DD; ++d) z += q[d] * sKsF[d];

    unsigned long long acc[16];
#pragma unroll
    for (int p = 0; p < 16; ++p) acc[p] = 0ull;

#pragma unroll
    for (int d = 0; d < DD; ++d) {
        const unsigned long long qd = pk(q[d], q[d]);
#pragma unroll
        for (int p = 0; p < 8; ++p) {
            const ulonglong2 kv2 = *(const ulonglong2*)&sKV[d][2 * p];
            fma2(acc[2 * p],     qd, kv2.x);
            fma2(acc[2 * p + 1], qd, kv2.y);
        }
    }

    const float inv = 1.0f / z;
    float* orow = out + ((size_t)n * LQ + l) * (HH * DD) + h * DD;
#pragma unroll
    for (int t2 = 0; t2 < 8; ++t2) {
        const float2 a = upk(acc[2 * t2]);
        const float2 b = upk(acc[2 * t2 + 1]);
        *(float4*)(orow + t2 * 4) = make_float4(a.x * inv, a.y * inv, b.x * inv, b.y * inv);
    }
}

extern "C" void kernel_launch(void* const* d_in, const int* in_sizes, int n_in,
                              void* d_out, int out_size) {
    (void)in_sizes; (void)n_in; (void)out_size;
    const float* q = (const float*)d_in[0];
    const float* k = (const float*)d_in[1];
    const float* v = (const float*)d_in[2];
    float* out = (float*)d_out;

    zero_kernel<<<(NH * DD * DD + 255) / 256, 256>>>();
    pass1<<<dim3(CHUNKS, NH), 256>>>(k, v);
    pass2<<<dim3(LQ / LT, NH), 256>>>(q, out);
}